// round 10
// baseline (speedup 1.0000x reference)
#include <cuda_runtime.h>
#include <cstdint>
#include <cstddef>

#define D0      128
#define NGRP    64
#define NB      256
#define TTOT    2560
#define NTILES  (NB * NGRP)     // 16384
#define NQUADS  (NTILES / 4)    // 4096
#define GRID    152             // 1 CTA per SM
#define THREADS 160             // warps 0..3 consumers (one per class), warp 4 producer
#define NSTAGES 12
#define NSPLIT  4               // bulk copies per tile

// ---------------- PTX helpers ----------------
__device__ __forceinline__ uint32_t smem_u32(const void* p) {
    return (uint32_t)__cvta_generic_to_shared(p);
}
__device__ __forceinline__ void mbar_init(uint32_t mbar, uint32_t cnt) {
    asm volatile("mbarrier.init.shared.b64 [%0], %1;" :: "r"(mbar), "r"(cnt) : "memory");
}
__device__ __forceinline__ void mbar_expect_tx(uint32_t mbar, uint32_t bytes) {
    asm volatile("mbarrier.arrive.expect_tx.shared.b64 _, [%0], %1;"
                 :: "r"(mbar), "r"(bytes) : "memory");
}
__device__ __forceinline__ void mbar_arrive(uint32_t mbar) {
    asm volatile("mbarrier.arrive.shared.b64 _, [%0];" :: "r"(mbar) : "memory");
}
__device__ __forceinline__ void bulk_g2s(uint32_t dst, const void* src,
                                         uint32_t bytes, uint32_t mbar) {
    asm volatile("cp.async.bulk.shared::cluster.global.mbarrier::complete_tx::bytes "
                 "[%0], [%1], %2, [%3];"
                 :: "r"(dst), "l"(src), "r"(bytes), "r"(mbar) : "memory");
}
__device__ __forceinline__ void mbar_wait(uint32_t mbar, uint32_t parity) {
    asm volatile(
        "{\n\t.reg .pred P;\n"
        "WL%=:\n\t"
        "mbarrier.try_wait.parity.acquire.cta.shared::cta.b64 P, [%0], %1, 0x989680;\n\t"
        "@P bra WD%=;\n\t"
        "bra WL%=;\n"
        "WD%=:\n\t}"
        :: "r"(mbar), "r"(parity) : "memory");
}
__device__ __forceinline__ void fence_async() {
    asm volatile("fence.proxy.async.shared::cta;" ::: "memory");
}

// class c (tile tokens 16*(c+1)) -> private sub-ring of stages
// counts {4,3,3,2}; float sizes {2048,4096,6144,8192}
// float bases: c0: 0; c1: 8192; c2: 20480; c3: 38912; total 55296 f = 216 KB
__device__ __constant__ int C_NC[4]   = { 4, 3, 3, 2 };
__device__ __constant__ int C_SZF[4]  = { 2048, 4096, 6144, 8192 };
__device__ __constant__ int C_BASE[4] = { 0, 8192, 20480, 38912 };
__device__ __constant__ int C_SIDX[4] = { 0, 4, 7, 10 };

extern __shared__ float dynbuf[];   // 216 KB

__global__ __launch_bounds__(THREADS, 1)
void ragged_attn_ws6(const float* __restrict__ s_i,
                     const float* __restrict__ theta,
                     float* __restrict__ out)
{
    __shared__ __align__(8)  unsigned long long full_b[NSTAGES];
    __shared__ __align__(8)  unsigned long long empty_b[NSTAGES];
    __shared__ __align__(16) float scores[4][64];

    const int tid  = threadIdx.x;
    const int lane = tid & 31;
    const int w    = tid >> 5;

    // quad-aligned tile range: class of tile l is exactly l&3
    const int qs    = (int)(((long long)blockIdx.x       * NQUADS) / GRID);
    const int qe    = (int)(((long long)(blockIdx.x + 1) * NQUADS) / GRID);
    const int start = qs * 4;
    const int n     = (qe - qs) * 4;

    if (tid == 0) {
        #pragma unroll
        for (int s = 0; s < NSTAGES; s++) {
            mbar_init(smem_u32(&full_b[s]), 1);
            mbar_init(smem_u32(&empty_b[s]), 1);
        }
    }
    __syncthreads();   // only block barrier

    if (w == 4) {
        // ===== producer warp: lanes 0..11, one stage each, independent loops =====
        if (lane < NSTAGES) {
            int c, j;
            if      (lane < 4)  { c = 0; j = lane;      }
            else if (lane < 7)  { c = 1; j = lane - 4;  }
            else if (lane < 10) { c = 2; j = lane - 7;  }
            else                { c = 3; j = lane - 10; }

            const int nc  = C_NC[c];
            const int sid = C_SIDX[c] + j;
            const uint32_t fb  = smem_u32(&full_b[sid]);
            const uint32_t eb  = smem_u32(&empty_b[sid]);
            const uint32_t dst = smem_u32(dynbuf + C_BASE[c] + j * C_SZF[c]);
            const int nt = (c + 1) << 4;
            const uint32_t bytes  = (uint32_t)nt * D0 * 4u;
            const uint32_t qbytes = bytes / NSPLIT;

            for (int m = 0; ; m++) {
                const int l = 4 * (j + nc * m) + c;
                if (l >= n) break;

                mbar_wait(eb, ((uint32_t)m & 1u) ^ 1u);   // m=0 passes fresh barrier

                const int id = start + l;
                const int g  = id & 63;
                const int t0 = (g >> 2) * 160 + c * (c + 1) * 8;
                const char* src = (const char*)
                    (theta + ((size_t)(id >> 6) * TTOT + t0) * D0);

                fence_async();
                mbar_expect_tx(fb, bytes);
                #pragma unroll
                for (int p = 0; p < NSPLIT; p++)
                    bulk_g2s(dst + p * qbytes, src + p * qbytes, qbytes, fb);
            }
        }
    } else {
        // ===== consumer warp w: ALL tiles of class w, in order (single waiter) =====
        const int c   = w;
        const int nt  = (c + 1) << 4;
        const int nc  = C_NC[c];
        const int gid = lane >> 3;     // 8-lane token group 0..3
        const int sub = lane & 7;      // d-quarter within token
        float* const srow = scores[w];

        for (int k = 0; ; k++) {
            const int l = 4 * k + c;
            if (l >= n) break;
            const int j = k % nc;
            const int m = k / nc;
            const int sid = C_SIDX[c] + j;
            const uint32_t fb = smem_u32(&full_b[sid]);
            const uint32_t eb = smem_u32(&empty_b[sid]);
            const float*  buf = dynbuf + C_BASE[c] + j * C_SZF[c];
            const float4* t4  = reinterpret_cast<const float4*>(buf);

            mbar_wait(fb, (uint32_t)(m & 1));

            const int id = start + l;
            const int b  = id >> 6;
            const int g  = id & 63;

            const float4* const s4p =
                reinterpret_cast<const float4*>(s_i + (size_t)b * D0);
            const float4 s0 = __ldg(s4p + sub);
            const float4 s1 = __ldg(s4p + sub + 8);
            const float4 s2 = __ldg(s4p + sub + 16);
            const float4 s3 = __ldg(s4p + sub + 24);

            // ---- phase A: scores; 4 tokens per pass, 8 lanes per token ----
            #pragma unroll 4
            for (int tk = gid; tk < nt; tk += 4) {
                const float4 v0 = t4[tk * 32 + sub];
                const float4 v1 = t4[tk * 32 + sub + 8];
                const float4 v2 = t4[tk * 32 + sub + 16];
                const float4 v3 = t4[tk * 32 + sub + 24];
                float x = v0.x*s0.x + v0.y*s0.y + v0.z*s0.z + v0.w*s0.w
                        + v1.x*s1.x + v1.y*s1.y + v1.z*s1.z + v1.w*s1.w
                        + v2.x*s2.x + v2.y*s2.y + v2.z*s2.z + v2.w*s2.w
                        + v3.x*s3.x + v3.y*s3.y + v3.z*s3.z + v3.w*s3.w;
                x += __shfl_xor_sync(0xffffffffu, x, 4);
                x += __shfl_xor_sync(0xffffffffu, x, 2);
                x += __shfl_xor_sync(0xffffffffu, x, 1);
                if (sub == 0) srow[tk] = x * (1.0f / 128.0f);   // / d0
            }
            __syncwarp();

            // ---- phase B: in-warp softmax; weights kept in registers ----
            const float a0 = (lane      < nt) ? srow[lane]      : -3.4e38f;
            const float a1 = (lane + 32 < nt) ? srow[lane + 32] : -3.4e38f;
            float mx = fmaxf(a0, a1);
            #pragma unroll
            for (int o = 16; o > 0; o >>= 1)
                mx = fmaxf(mx, __shfl_xor_sync(0xffffffffu, mx, o));
            const float e0 = (lane      < nt) ? __expf(a0 - mx) : 0.0f;
            const float e1 = (lane + 32 < nt) ? __expf(a1 - mx) : 0.0f;
            float sd = e0 + e1;
            #pragma unroll
            for (int o = 16; o > 0; o >>= 1)
                sd += __shfl_xor_sync(0xffffffffu, sd, o);
            const float inv = 1.0f / sd;
            const float wl = e0 * inv;
            const float wh = e1 * inv;

            // ---- phase C: weighted sum; weights broadcast via shuffle ----
            float4 acc = make_float4(0.f, 0.f, 0.f, 0.f);
            for (int t = 0; t < nt; t += 4) {
                const float base = (t < 32) ? wl : wh;
                const float w0 = __shfl_sync(0xffffffffu, base, (t + 0) & 31);
                const float w1 = __shfl_sync(0xffffffffu, base, (t + 1) & 31);
                const float w2 = __shfl_sync(0xffffffffu, base, (t + 2) & 31);
                const float w3 = __shfl_sync(0xffffffffu, base, (t + 3) & 31);
                const float4 va = t4[(t + 0) * 32 + lane];
                const float4 vb = t4[(t + 1) * 32 + lane];
                const float4 vc = t4[(t + 2) * 32 + lane];
                const float4 vd = t4[(t + 3) * 32 + lane];
                acc.x += w0*va.x + w1*vb.x + w2*vc.x + w3*vd.x;
                acc.y += w0*va.y + w1*vb.y + w2*vc.y + w3*vd.y;
                acc.z += w0*va.z + w1*vb.z + w2*vc.z + w3*vd.z;
                acc.w += w0*va.w + w1*vb.w + w2*vc.w + w3*vd.w;
            }
            reinterpret_cast<float4*>(out + ((size_t)b * NGRP + g) * D0)[lane] = acc;

            __syncwarp();                      // all lanes done reading buf
            if (lane == 0) mbar_arrive(eb);    // stage free for next fill
        }
    }
}

extern "C" void kernel_launch(void* const* d_in, const int* in_sizes, int n_in,
                              void* d_out, int out_size)
{
    const float* s_i   = (const float*)d_in[0];   // [256,128]
    const float* theta = (const float*)d_in[1];   // [256,2560,128]
    float* out = (float*)d_out;                   // [256,64,128]
    (void)in_sizes; (void)n_in; (void)out_size;

    const size_t dyn = 55296 * sizeof(float);     // 216 KB
    cudaFuncSetAttribute(ragged_attn_ws6,
                         cudaFuncAttributeMaxDynamicSharedMemorySize, (int)dyn);
    ragged_attn_ws6<<<GRID, THREADS, dyn>>>(s_i, theta, out);
}

// round 11
// speedup vs baseline: 1.2825x; 1.2825x over previous
#include <cuda_runtime.h>
#include <cstdint>
#include <cstddef>

#define D0      128
#define NGRP    64
#define NB      256
#define TTOT    2560
#define NQUADS  4096            // 16384 tiles / 4 per size-cycle
#define GRID    152             // 1 CTA per SM
#define THREADS 512             // w0-5 TMA consumers, w7 producer, w8-15 direct
#define NTC     6               // TMA consumer warps / stages
#define NDIR    8               // direct-LDG warps
#define STAGE_F (64 * D0)       // 32 KB stage
#define NSPLIT  4

// ---------------- PTX helpers ----------------
__device__ __forceinline__ uint32_t smem_u32(const void* p) {
    return (uint32_t)__cvta_generic_to_shared(p);
}
__device__ __forceinline__ void mbar_init(uint32_t mbar, uint32_t cnt) {
    asm volatile("mbarrier.init.shared.b64 [%0], %1;" :: "r"(mbar), "r"(cnt) : "memory");
}
__device__ __forceinline__ void mbar_expect_tx(uint32_t mbar, uint32_t bytes) {
    asm volatile("mbarrier.arrive.expect_tx.shared.b64 _, [%0], %1;"
                 :: "r"(mbar), "r"(bytes) : "memory");
}
__device__ __forceinline__ void mbar_arrive(uint32_t mbar) {
    asm volatile("mbarrier.arrive.shared.b64 _, [%0];" :: "r"(mbar) : "memory");
}
__device__ __forceinline__ void bulk_g2s(uint32_t dst, const void* src,
                                         uint32_t bytes, uint32_t mbar) {
    asm volatile("cp.async.bulk.shared::cluster.global.mbarrier::complete_tx::bytes "
                 "[%0], [%1], %2, [%3];"
                 :: "r"(dst), "l"(src), "r"(bytes), "r"(mbar) : "memory");
}
__device__ __forceinline__ void mbar_wait(uint32_t mbar, uint32_t parity) {
    asm volatile(
        "{\n\t.reg .pred P;\n"
        "WL%=:\n\t"
        "mbarrier.try_wait.parity.acquire.cta.shared::cta.b64 P, [%0], %1, 0x989680;\n\t"
        "@P bra WD%=;\n\t"
        "bra WL%=;\n"
        "WD%=:\n\t}"
        :: "r"(mbar), "r"(parity) : "memory");
}
__device__ __forceinline__ void fence_async() {
    asm volatile("fence.proxy.async.shared::cta;" ::: "memory");
}

extern __shared__ float dynbuf[];   // NTC * 32 KB = 192 KB

__global__ __launch_bounds__(THREADS, 1)
void ragged_attn_hy(const float* __restrict__ s_i,
                    const float* __restrict__ theta,
                    float* __restrict__ out)
{
    __shared__ __align__(8)  unsigned long long full_b[NTC];
    __shared__ __align__(8)  unsigned long long empty_b[NTC];
    __shared__ __align__(16) float scores_t[NTC][64];
    __shared__ __align__(16) float scores_d[NDIR][64];

    const int tid  = threadIdx.x;
    const int lane = tid & 31;
    const int w    = tid >> 5;
    const int gid  = lane >> 3;     // 8-lane token group 0..3
    const int sub  = lane & 7;      // d-quarter within token

    // quad range for this CTA
    const int qs = (int)(((long long)blockIdx.x       * NQUADS) / GRID);
    const int qe = (int)(((long long)(blockIdx.x + 1) * NQUADS) / GRID);
    const int n2 = (qe - qs) * 2;   // heavy (and light) tile counts

    if (tid == 0) {
        #pragma unroll
        for (int s = 0; s < NTC; s++) {
            mbar_init(smem_u32(&full_b[s]), 1);
            mbar_init(smem_u32(&empty_b[s]), 1);
        }
    }
    __syncthreads();   // only block barrier

    if (w == 7) {
        // ===== TMA producer: lanes 0..5 each own stage s, fill i = k*6+s =====
        const int s = lane;
        if (s < NTC) {
            const uint32_t fb  = smem_u32(&full_b[s]);
            const uint32_t eb  = smem_u32(&empty_b[s]);
            const uint32_t dst = smem_u32(dynbuf + s * STAGE_F);
            const int c  = 2 + (s & 1);              // i&1 == s&1 (stride 6)
            const int nt = (c + 1) << 4;             // 48 or 64
            const uint32_t bytes  = (uint32_t)nt * D0 * 4u;
            const uint32_t qbytes = bytes / NSPLIT;

            for (int k = 0; ; k++) {
                const int i = k * NTC + s;
                if (i >= n2) break;
                mbar_wait(eb, ((uint32_t)k & 1u) ^ 1u);

                const int id = (qs + (i >> 1)) * 4 + c;
                const int g  = id & 63;
                const int t0 = (g >> 2) * 160 + c * (c + 1) * 8;
                const char* src = (const char*)
                    (theta + ((size_t)(id >> 6) * TTOT + t0) * D0);

                fence_async();
                mbar_expect_tx(fb, bytes);
                #pragma unroll
                for (int p = 0; p < NSPLIT; p++)
                    bulk_g2s(dst + p * qbytes, src + p * qbytes, qbytes, fb);
            }
        }
    } else if (w < NTC) {
        // ===== TMA consumer warp w: heavy tiles i = k*6 + w (class 2 or 3) =====
        const int c  = 2 + (w & 1);
        const int nt = (c + 1) << 4;                 // 48 or 64, loop-invariant
        float* const srow = scores_t[w];
        const uint32_t fb = smem_u32(&full_b[w]);
        const uint32_t eb = smem_u32(&empty_b[w]);
        const float4* t4  = reinterpret_cast<const float4*>(dynbuf + w * STAGE_F);

        for (int k = 0; ; k++) {
            const int i = k * NTC + w;
            if (i >= n2) break;
            mbar_wait(fb, (uint32_t)(k & 1));

            const int id = (qs + (i >> 1)) * 4 + c;
            const int b  = id >> 6;
            const int g  = id & 63;

            const float4* const s4p =
                reinterpret_cast<const float4*>(s_i + (size_t)b * D0);
            const float4 s0 = __ldg(s4p + sub);
            const float4 s1 = __ldg(s4p + sub + 8);
            const float4 s2 = __ldg(s4p + sub + 16);
            const float4 s3 = __ldg(s4p + sub + 24);

            // phase A
            #pragma unroll 4
            for (int tk = gid; tk < nt; tk += 4) {
                const float4 v0 = t4[tk * 32 + sub];
                const float4 v1 = t4[tk * 32 + sub + 8];
                const float4 v2 = t4[tk * 32 + sub + 16];
                const float4 v3 = t4[tk * 32 + sub + 24];
                float x = v0.x*s0.x + v0.y*s0.y + v0.z*s0.z + v0.w*s0.w
                        + v1.x*s1.x + v1.y*s1.y + v1.z*s1.z + v1.w*s1.w
                        + v2.x*s2.x + v2.y*s2.y + v2.z*s2.z + v2.w*s2.w
                        + v3.x*s3.x + v3.y*s3.y + v3.z*s3.z + v3.w*s3.w;
                x += __shfl_xor_sync(0xffffffffu, x, 4);
                x += __shfl_xor_sync(0xffffffffu, x, 2);
                x += __shfl_xor_sync(0xffffffffu, x, 1);
                if (sub == 0) srow[tk] = x * (1.0f / 128.0f);
            }
            __syncwarp();

            // phase B
            const float a0 = (lane      < nt) ? srow[lane]      : -3.4e38f;
            const float a1 = (lane + 32 < nt) ? srow[lane + 32] : -3.4e38f;
            float mx = fmaxf(a0, a1);
            #pragma unroll
            for (int o = 16; o > 0; o >>= 1)
                mx = fmaxf(mx, __shfl_xor_sync(0xffffffffu, mx, o));
            const float e0 = (lane      < nt) ? __expf(a0 - mx) : 0.0f;
            const float e1 = (lane + 32 < nt) ? __expf(a1 - mx) : 0.0f;
            float sd = e0 + e1;
            #pragma unroll
            for (int o = 16; o > 0; o >>= 1)
                sd += __shfl_xor_sync(0xffffffffu, sd, o);
            const float inv = 1.0f / sd;
            const float wl = e0 * inv;
            const float wh = e1 * inv;

            // phase C
            float4 acc = make_float4(0.f, 0.f, 0.f, 0.f);
            for (int t = 0; t < nt; t += 4) {
                const float base = (t < 32) ? wl : wh;
                const float w0 = __shfl_sync(0xffffffffu, base, (t + 0) & 31);
                const float w1 = __shfl_sync(0xffffffffu, base, (t + 1) & 31);
                const float w2 = __shfl_sync(0xffffffffu, base, (t + 2) & 31);
                const float w3 = __shfl_sync(0xffffffffu, base, (t + 3) & 31);
                const float4 va = t4[(t + 0) * 32 + lane];
                const float4 vb = t4[(t + 1) * 32 + lane];
                const float4 vc = t4[(t + 2) * 32 + lane];
                const float4 vd = t4[(t + 3) * 32 + lane];
                acc.x += w0*va.x + w1*vb.x + w2*vc.x + w3*vd.x;
                acc.y += w0*va.y + w1*vb.y + w2*vc.y + w3*vd.y;
                acc.z += w0*va.z + w1*vb.z + w2*vc.z + w3*vd.z;
                acc.w += w0*va.w + w1*vb.w + w2*vc.w + w3*vd.w;
            }
            reinterpret_cast<float4*>(out + ((size_t)b * NGRP + g) * D0)[lane] = acc;

            __syncwarp();
            if (lane == 0) mbar_arrive(eb);
        }
    } else if (w >= 8) {
        // ===== direct-LDG warp: light tiles j = k*8 + (w-8) (class 0 or 1) =====
        const int dw = w - 8;
        const int c  = dw & 1;                       // j&1 == dw&1 (stride 8)
        const int nt = (c + 1) << 4;                 // 16 or 32
        float* const srow = scores_d[dw];

        for (int k = 0; ; k++) {
            const int j = k * NDIR + dw;
            if (j >= n2) break;

            const int id = (qs + (j >> 1)) * 4 + c;
            const int b  = id >> 6;
            const int g  = id & 63;
            const int t0 = (g >> 2) * 160 + c * (c + 1) * 8;
            const float4* g4 = reinterpret_cast<const float4*>(
                theta + ((size_t)b * TTOT + t0) * D0);

            const float4* const s4p =
                reinterpret_cast<const float4*>(s_i + (size_t)b * D0);
            const float4 s0 = __ldg(s4p + sub);
            const float4 s1 = __ldg(s4p + sub + 8);
            const float4 s2 = __ldg(s4p + sub + 16);
            const float4 s3 = __ldg(s4p + sub + 24);

            // pass 1: stream from DRAM, fused dot (leaves tile in L2)
            #pragma unroll 4
            for (int tk = gid; tk < nt; tk += 4) {
                const float4 v0 = __ldg(g4 + tk * 32 + sub);
                const float4 v1 = __ldg(g4 + tk * 32 + sub + 8);
                const float4 v2 = __ldg(g4 + tk * 32 + sub + 16);
                const float4 v3 = __ldg(g4 + tk * 32 + sub + 24);
                float x = v0.x*s0.x + v0.y*s0.y + v0.z*s0.z + v0.w*s0.w
                        + v1.x*s1.x + v1.y*s1.y + v1.z*s1.z + v1.w*s1.w
                        + v2.x*s2.x + v2.y*s2.y + v2.z*s2.z + v2.w*s2.w
                        + v3.x*s3.x + v3.y*s3.y + v3.z*s3.z + v3.w*s3.w;
                x += __shfl_xor_sync(0xffffffffu, x, 4);
                x += __shfl_xor_sync(0xffffffffu, x, 2);
                x += __shfl_xor_sync(0xffffffffu, x, 1);
                if (sub == 0) srow[tk] = x * (1.0f / 128.0f);
            }
            __syncwarp();

            // softmax (nt <= 32 here, upper half disabled)
            const float a0 = (lane < nt) ? srow[lane] : -3.4e38f;
            float mx = a0;
            #pragma unroll
            for (int o = 16; o > 0; o >>= 1)
                mx = fmaxf(mx, __shfl_xor_sync(0xffffffffu, mx, o));
            const float e0 = (lane < nt) ? __expf(a0 - mx) : 0.0f;
            float sd = e0;
            #pragma unroll
            for (int o = 16; o > 0; o >>= 1)
                sd += __shfl_xor_sync(0xffffffffu, sd, o);
            const float wl = e0 * (1.0f / sd);

            // pass 2: re-read from L2, weighted sum
            float4 acc = make_float4(0.f, 0.f, 0.f, 0.f);
            for (int t = 0; t < nt; t += 4) {
                const float w0 = __shfl_sync(0xffffffffu, wl, t + 0);
                const float w1 = __shfl_sync(0xffffffffu, wl, t + 1);
                const float w2 = __shfl_sync(0xffffffffu, wl, t + 2);
                const float w3 = __shfl_sync(0xffffffffu, wl, t + 3);
                const float4 va = __ldg(g4 + (t + 0) * 32 + lane);
                const float4 vb = __ldg(g4 + (t + 1) * 32 + lane);
                const float4 vc = __ldg(g4 + (t + 2) * 32 + lane);
                const float4 vd = __ldg(g4 + (t + 3) * 32 + lane);
                acc.x += w0*va.x + w1*vb.x + w2*vc.x + w3*vd.x;
                acc.y += w0*va.y + w1*vb.y + w2*vc.y + w3*vd.y;
                acc.z += w0*va.z + w1*vb.z + w2*vc.z + w3*vd.z;
                acc.w += w0*va.w + w1*vb.w + w2*vc.w + w3*vd.w;
            }
            reinterpret_cast<float4*>(out + ((size_t)b * NGRP + g) * D0)[lane] = acc;
        }
    }
    // warp 6 idle (kept for simple stage<->warp mapping)
}

extern "C" void kernel_launch(void* const* d_in, const int* in_sizes, int n_in,
                              void* d_out, int out_size)
{
    const float* s_i   = (const float*)d_in[0];   // [256,128]
    const float* theta = (const float*)d_in[1];   // [256,2560,128]
    float* out = (float*)d_out;                   // [256,64,128]
    (void)in_sizes; (void)n_in; (void)out_size;

    const size_t dyn = (size_t)NTC * STAGE_F * sizeof(float);   // 192 KB
    cudaFuncSetAttribute(ragged_attn_hy,
                         cudaFuncAttributeMaxDynamicSharedMemorySize, (int)dyn);
    ragged_attn_hy<<<GRID, THREADS, dyn>>>(s_i, theta, out);
}

// round 12
// speedup vs baseline: 1.3673x; 1.0661x over previous
#include <cuda_runtime.h>
#include <cstdint>
#include <cstddef>

#define D0      128
#define NGRP    64
#define NB      256
#define TTOT    2560
#define NQUADS  4096            // 16384 tiles / 4-tile size cycle
#define GRID    152             // 1 CTA per SM
#define NWARPS  10              // all workers, class-pinned
#define THREADS (NWARPS * 32)
#define NSPLIT  4

// ---------------- PTX helpers ----------------
__device__ __forceinline__ uint32_t smem_u32(const void* p) {
    return (uint32_t)__cvta_generic_to_shared(p);
}
__device__ __forceinline__ void mbar_init(uint32_t mbar, uint32_t cnt) {
    asm volatile("mbarrier.init.shared.b64 [%0], %1;" :: "r"(mbar), "r"(cnt) : "memory");
}
__device__ __forceinline__ void mbar_expect_tx(uint32_t mbar, uint32_t bytes) {
    asm volatile("mbarrier.arrive.expect_tx.shared.b64 _, [%0], %1;"
                 :: "r"(mbar), "r"(bytes) : "memory");
}
__device__ __forceinline__ void bulk_g2s(uint32_t dst, const void* src,
                                         uint32_t bytes, uint32_t mbar) {
    asm volatile("cp.async.bulk.shared::cluster.global.mbarrier::complete_tx::bytes "
                 "[%0], [%1], %2, [%3];"
                 :: "r"(dst), "l"(src), "r"(bytes), "r"(mbar) : "memory");
}
__device__ __forceinline__ void mbar_wait(uint32_t mbar, uint32_t parity) {
    asm volatile(
        "{\n\t.reg .pred P;\n"
        "WL%=:\n\t"
        "mbarrier.try_wait.parity.acquire.cta.shared::cta.b64 P, [%0], %1, 0x989680;\n\t"
        "@P bra WD%=;\n\t"
        "bra WL%=;\n"
        "WD%=:\n\t}"
        :: "r"(mbar), "r"(parity) : "memory");
}
__device__ __forceinline__ void fence_async() {
    asm volatile("fence.proxy.async.shared::cta;" ::: "memory");
}

// warp -> (class, index-in-class, warps-in-class, buffer float offset)
// classes sized 16/32/48/64 tokens = 8/16/24/32 KB; warps per class {2,2,3,3}
__device__ __constant__ int W_C[NWARPS]   = { 0,0, 1,1, 2,2,2, 3,3,3 };
__device__ __constant__ int W_J[NWARPS]   = { 0,1, 0,1, 0,1,2, 0,1,2 };
__device__ __constant__ int W_NW[NWARPS]  = { 2,2, 2,2, 3,3,3, 3,3,3 };
__device__ __constant__ int W_OFF[NWARPS] = { 0, 2048, 4096, 8192,
                                              12288, 18432, 24576,
                                              30720, 38912, 47104 };   // 55296 fl total

extern __shared__ float dynbuf[];   // 216 KB

__global__ __launch_bounds__(THREADS, 1)
void ragged_attn_sr(const float* __restrict__ s_i,
                    const float* __restrict__ theta,
                    float* __restrict__ out)
{
    __shared__ __align__(8)  unsigned long long full_b[NWARPS];
    __shared__ __align__(16) float scores[NWARPS][64];

    const int tid  = threadIdx.x;
    const int lane = tid & 31;
    const int w    = tid >> 5;
    const int gid  = lane >> 3;     // 8-lane token group 0..3
    const int sub  = lane & 7;      // d-quarter within token

    // quad-aligned tile range: class of tile l is l&3
    const int qs    = (int)(((long long)blockIdx.x       * NQUADS) / GRID);
    const int qe    = (int)(((long long)(blockIdx.x + 1) * NQUADS) / GRID);
    const int start = qs * 4;
    const int n     = (qe - qs) * 4;

    if (tid == 0) {
        #pragma unroll
        for (int s = 0; s < NWARPS; s++) mbar_init(smem_u32(&full_b[s]), 1);
    }
    __syncthreads();   // only block barrier

    const int c  = W_C[w];
    const int jw = W_J[w];
    const int nw = W_NW[w];
    const int nt = (c + 1) << 4;                     // loop-invariant tokens
    const uint32_t bytes  = (uint32_t)nt * D0 * 4u;
    const uint32_t qbytes = bytes / NSPLIT;
    const uint32_t fb  = smem_u32(&full_b[w]);
    float* const  buf  = dynbuf + W_OFF[w];
    const uint32_t dst = smem_u32(buf);
    const float4* t4   = reinterpret_cast<const float4*>(buf);
    float* const  srow = scores[w];

    // source address of tile l (class c fixed)
    auto src_of = [&](int l) -> const char* {
        const int id = start + l;
        const int g  = id & 63;
        const int t0 = (g >> 2) * 160 + c * (c + 1) * 8;
        return (const char*)(theta + ((size_t)(id >> 6) * TTOT + t0) * D0);
    };

    // prologue: issue first fill
    {
        const int l0 = 4 * jw + c;
        if (l0 < n && lane == 0) {
            mbar_expect_tx(fb, bytes);
            #pragma unroll
            for (int p = 0; p < NSPLIT; p++)
                bulk_g2s(dst + p * qbytes, src_of(l0) + p * qbytes, qbytes, fb);
        }
    }

    for (int k = 0; ; k++) {
        const int l = 4 * (jw + nw * k) + c;
        if (l >= n) break;

        mbar_wait(fb, (uint32_t)(k & 1));            // single-waiter, in order

        const int id = start + l;
        const int b  = id >> 6;
        const int g  = id & 63;

        const float4* const s4p =
            reinterpret_cast<const float4*>(s_i + (size_t)b * D0);
        const float4 s0 = __ldg(s4p + sub);
        const float4 s1 = __ldg(s4p + sub + 8);
        const float4 s2 = __ldg(s4p + sub + 16);
        const float4 s3 = __ldg(s4p + sub + 24);

        // ---- phase A: scores; 4 tokens per pass, 8 lanes per token ----
        #pragma unroll 4
        for (int tk = gid; tk < nt; tk += 4) {
            const float4 v0 = t4[tk * 32 + sub];
            const float4 v1 = t4[tk * 32 + sub + 8];
            const float4 v2 = t4[tk * 32 + sub + 16];
            const float4 v3 = t4[tk * 32 + sub + 24];
            float x = v0.x*s0.x + v0.y*s0.y + v0.z*s0.z + v0.w*s0.w
                    + v1.x*s1.x + v1.y*s1.y + v1.z*s1.z + v1.w*s1.w
                    + v2.x*s2.x + v2.y*s2.y + v2.z*s2.z + v2.w*s2.w
                    + v3.x*s3.x + v3.y*s3.y + v3.z*s3.z + v3.w*s3.w;
            x += __shfl_xor_sync(0xffffffffu, x, 4);
            x += __shfl_xor_sync(0xffffffffu, x, 2);
            x += __shfl_xor_sync(0xffffffffu, x, 1);
            if (sub == 0) srow[tk] = x * (1.0f / 128.0f);   // / d0
        }
        __syncwarp();

        // ---- phase B: in-warp softmax; weights kept in registers ----
        const float a0 = (lane      < nt) ? srow[lane]      : -3.4e38f;
        const float a1 = (lane + 32 < nt) ? srow[lane + 32] : -3.4e38f;
        float mx = fmaxf(a0, a1);
        #pragma unroll
        for (int o = 16; o > 0; o >>= 1)
            mx = fmaxf(mx, __shfl_xor_sync(0xffffffffu, mx, o));
        const float e0 = (lane      < nt) ? __expf(a0 - mx) : 0.0f;
        const float e1 = (lane + 32 < nt) ? __expf(a1 - mx) : 0.0f;
        float sd = e0 + e1;
        #pragma unroll
        for (int o = 16; o > 0; o >>= 1)
            sd += __shfl_xor_sync(0xffffffffu, sd, o);
        const float inv = 1.0f / sd;
        const float wl = e0 * inv;
        const float wh = e1 * inv;

        // ---- phase C: weighted sum; weights broadcast via shuffle ----
        float4 acc = make_float4(0.f, 0.f, 0.f, 0.f);
        for (int t = 0; t < nt; t += 4) {
            const float base = (t < 32) ? wl : wh;
            const float w0 = __shfl_sync(0xffffffffu, base, (t + 0) & 31);
            const float w1 = __shfl_sync(0xffffffffu, base, (t + 1) & 31);
            const float w2 = __shfl_sync(0xffffffffu, base, (t + 2) & 31);
            const float w3 = __shfl_sync(0xffffffffu, base, (t + 3) & 31);
            const float4 va = t4[(t + 0) * 32 + lane];
            const float4 vb = t4[(t + 1) * 32 + lane];
            const float4 vc = t4[(t + 2) * 32 + lane];
            const float4 vd = t4[(t + 3) * 32 + lane];
            acc.x += w0*va.x + w1*vb.x + w2*vc.x + w3*vd.x;
            acc.y += w0*va.y + w1*vb.y + w2*vc.y + w3*vd.y;
            acc.z += w0*va.z + w1*vb.z + w2*vc.z + w3*vd.z;
            acc.w += w0*va.w + w1*vb.w + w2*vc.w + w3*vd.w;
        }
        reinterpret_cast<float4*>(out + ((size_t)b * NGRP + g) * D0)[lane] = acc;

        __syncwarp();   // all lanes' buffer reads complete (values in registers)

        // ---- self-refill: issue next fill into our own (now free) buffer ----
        const int ln = 4 * (jw + nw * (k + 1)) + c;
        if (ln < n && lane == 0) {
            fence_async();
            mbar_expect_tx(fb, bytes);
            #pragma unroll
            for (int p = 0; p < NSPLIT; p++)
                bulk_g2s(dst + p * qbytes, src_of(ln) + p * qbytes, qbytes, fb);
        }
    }
}

extern "C" void kernel_launch(void* const* d_in, const int* in_sizes, int n_in,
                              void* d_out, int out_size)
{
    const float* s_i   = (const float*)d_in[0];   // [256,128]
    const float* theta = (const float*)d_in[1];   // [256,2560,128]
    float* out = (float*)d_out;                   // [256,64,128]
    (void)in_sizes; (void)n_in; (void)out_size;

    const size_t dyn = 55296 * sizeof(float);     // 216 KB
    cudaFuncSetAttribute(ragged_attn_sr,
                         cudaFuncAttributeMaxDynamicSharedMemorySize, (int)dyn);
    ragged_attn_sr<<<GRID, THREADS, dyn>>>(s_i, theta, out);
}